// round 11
// baseline (speedup 1.0000x reference)
#include <cuda_runtime.h>

// fired[b,s,r] = x[...,i] * x[...,5+j] * x[...,10+k],  r = i*25 + j*5 + k
// Exact zeros in x act as identity (reference: where(rpu==0,1,rpu)).
//
// R2-R8 lesson: time pinned ~6.7us across 4x instruction-count range, nothing
// saturated -> the shared CTA-wide phase structure (LDG burst -> barrier ->
// store burst, lockstep across the whole single wave) is the suspect.
// R9: warp-autonomous, zero smem, zero barriers. Warp owns 4 positions;
// lanes 0-14 hold the 15 membership values in registers; factors broadcast
// via __shfl_sync (runtime src). 12 SHFL + 8 FMUL + 4 coalesced STG.32 per
// position. Rule decomposition (r = lane + 32s) done once per warp.

static constexpr int F  = 15;    // membership functions per position
static constexpr int R  = 125;   // rules per position
static constexpr int PW = 4;     // positions per warp

__global__ void __launch_bounds__(256, 8)
rules_fire_v9(const float* __restrict__ x, float* __restrict__ out)
{
    const int lane = threadIdx.x & 31;
    const int gw   = (int)((blockIdx.x * blockDim.x + threadIdx.x) >> 5);
    const int p0   = gw * PW;                 // first position of this warp

    // Fixed per-lane rule slots: r = lane + 32*s  (s = 0..3, r < 125 active).
    int oa[4], ob[4], oc[4];
    bool act[4];
    #pragma unroll
    for (int s = 0; s < 4; s++) {
        const int r = lane + 32 * s;
        act[s] = (r < R);
        const int q = r / 5;
        const int k = r - 5 * q;              // r % 5
        const int i = q / 5;
        const int j = q - 5 * i;              // (r/5) % 5
        oa[s] = i;
        ob[s] = 5 + j;
        oc[s] = 10 + k;
    }

    // Load 4 positions' rows into registers (lane l < 15 holds x[p, l]),
    // zero->1 fix applied at load. Independent LDGs -> MLP=4.
    float v[PW];
    #pragma unroll
    for (int q = 0; q < PW; q++) {
        float val = 1.0f;
        if (lane < F) {
            val = x[(size_t)(p0 + q) * F + lane];
            val = (val == 0.0f) ? 1.0f : val;
        }
        v[q] = val;
    }

    // Compute + store. No barriers anywhere; warps fully independent.
    #pragma unroll
    for (int q = 0; q < PW; q++) {
        float* o = out + (size_t)(p0 + q) * R;
        #pragma unroll
        for (int s = 0; s < 4; s++) {
            const float a = __shfl_sync(0xffffffffu, v[q], oa[s]);
            const float b = __shfl_sync(0xffffffffu, v[q], ob[s]);
            const float c = __shfl_sync(0xffffffffu, v[q], oc[s]);
            if (act[s])
                o[lane + 32 * s] = a * b * c;   // (a*b)*c = jnp.prod order
        }
    }
}

// Scalar fallback for positions past the last full warp-group
// (unused for B=16,S=2048: 32768 % 4 == 0).
__global__ void rules_fire_tail(const float* __restrict__ x, float* __restrict__ out,
                                int pos0, int npos)
{
    const int pos = pos0 + blockIdx.x;
    if (pos >= npos) return;
    __shared__ float sxt[F + 1];
    const int t = threadIdx.x;
    if (t < F) {
        float v = x[(size_t)pos * F + t];
        sxt[t] = (v == 0.0f) ? 1.0f : v;
    }
    __syncthreads();
    if (t < R) {
        const int i = t / 25, j = (t / 5) % 5, k = t % 5;
        out[(size_t)pos * R + t] = sxt[i] * sxt[5 + j] * sxt[10 + k];
    }
}

extern "C" void kernel_launch(void* const* d_in, const int* in_sizes, int n_in,
                              void* d_out, int out_size)
{
    const float* x = (const float*)d_in[0];   // (B, S, 15) float32
    float* out = (float*)d_out;               // (B, S, 125) float32

    const int npos   = in_sizes[0] / F;       // 32768
    const int nwarps = npos / PW;             // 8192
    const int nblk   = nwarps / 8;            // 1024 CTAs x 8 warps
    if (nblk > 0)
        rules_fire_v9<<<nblk, 256>>>(x, out);

    const int done = nblk * 8 * PW;
    const int tail = npos - done;
    if (tail > 0)
        rules_fire_tail<<<tail, 128>>>(x, out, done, npos);
}

// round 12
// speedup vs baseline: 1.0295x; 1.0295x over previous
#include <cuda_runtime.h>

// fired[b,s,r] = x[...,i] * x[...,5+j] * x[...,10+k],  r = i*25 + j*5 + k
// Exact zeros in x act as identity (reference: where(rpu==0,1,rpu)).
//
// R2-R9: ~6.7us plateau across 8 structural variants, nothing saturated;
// warps stall ~70% in coincident windows (single-wave launch alignment).
// R10 probe: 64-thread CTAs (G=8, grid=4096) — fine-grained CTA scheduling
// decorrelates stall windows; CLC backfills completed CTAs independently.
// Body is R7's minimal form: immediate-offset LDS, 2 rules/thread,
// coalesced STG.32.

static constexpr int F    = 15;           // membership functions per position
static constexpr int R    = 125;          // rules per position
static constexpr int G    = 8;            // positions per CTA
static constexpr int NLD4 = G * F / 4;    // 30 float4 input loads per CTA

__global__ void __launch_bounds__(64, 32)
rules_fire_v10(const float4* __restrict__ x4, float* __restrict__ out)
{
    __shared__ float sx[G * F];           // 120 floats (8 rows x 15)

    const int t   = threadIdx.x;
    const int grp = blockIdx.x;

    // Stage 8x15 inputs (threads 0..29), zero->1 fix at load.
    if (t < NLD4) {
        float4 v = x4[(size_t)grp * NLD4 + t];
        v.x = (v.x == 0.0f) ? 1.0f : v.x;
        v.y = (v.y == 0.0f) ? 1.0f : v.y;
        v.z = (v.z == 0.0f) ? 1.0f : v.z;
        v.w = (v.w == 0.0f) ? 1.0f : v.w;
        reinterpret_cast<float4*>(sx)[t] = v;
    }
    __syncthreads();

    // Thread t handles rules t and t+64 (t+64 < 125 -> t < 61).
    // Decompositions are the only divisions; loop strides fold to immediates.
    {
        const int r0 = t;
        const int q0 = r0 / 5;
        const int k0 = r0 - 5 * q0;
        const int i0 = q0 / 5;
        const int j0 = q0 - 5 * i0;
        const int a0 = i0, b0 = 5 + j0, c0 = 10 + k0;

        const int r1 = t + 64;
        const bool act1 = (r1 < R);
        const int q1 = r1 / 5;
        const int k1 = r1 - 5 * q1;
        const int i1 = q1 / 5;
        const int j1 = q1 - 5 * i1;
        const int a1 = i1, b1 = 5 + j1, c1 = 10 + k1;

        float* o = out + (size_t)grp * G * R + t;

        #pragma unroll
        for (int p = 0; p < G; p++) {
            const int rb = p * F;             // LDS immediate
            const int ob = p * R;             // STG immediate
            o[ob] = sx[rb + a0] * sx[rb + b0] * sx[rb + c0];
            if (act1)
                o[ob + 64] = sx[rb + a1] * sx[rb + b1] * sx[rb + c1];
        }
    }
}

// Scalar fallback for positions past the last full group (unused for B=16,S=2048).
__global__ void rules_fire_tail(const float* __restrict__ x, float* __restrict__ out,
                                int pos0, int npos)
{
    const int pos = pos0 + blockIdx.x;
    if (pos >= npos) return;
    __shared__ float sxt[F + 1];
    const int t = threadIdx.x;
    if (t < F) {
        float v = x[(size_t)pos * F + t];
        sxt[t] = (v == 0.0f) ? 1.0f : v;
    }
    __syncthreads();
    if (t < R) {
        const int i = t / 25, j = (t / 5) % 5, k = t % 5;
        out[(size_t)pos * R + t] = sxt[i] * sxt[5 + j] * sxt[10 + k];
    }
}

extern "C" void kernel_launch(void* const* d_in, const int* in_sizes, int n_in,
                              void* d_out, int out_size)
{
    const float* x = (const float*)d_in[0];   // (B, S, 15) float32
    float* out = (float*)d_out;               // (B, S, 125) float32

    const int npos    = in_sizes[0] / F;      // 32768
    const int ngroups = npos / G;             // 4096
    if (ngroups > 0)
        rules_fire_v10<<<ngroups, 64>>>((const float4*)x, out);

    const int tail = npos - ngroups * G;
    if (tail > 0)
        rules_fire_tail<<<tail, 128>>>(x, out, ngroups * G, npos);
}